// round 3
// baseline (speedup 1.0000x reference)
#include <cuda_runtime.h>
#include <math_constants.h>

#define S_TOT 2048
#define B_DIM 64
#define N_DIM 256
#define EPSV 0.01f
#define INV_EPS 100.0f
#define THRESH 0.1f
#define MAX_ITER 100
#define LOG_EPS 1e-8f

// Global: E0_ij = exp((Cmin - C_ij)/eps), identical for all samples.
// 64KB, read-only after init -> lives in every SM's L1 (228KB) for the whole
// launch. No per-block shared staging needed.
__device__ float g_E0[B_DIM * N_DIM];
__device__ float g_Cmin;

// ---------------------------------------------------------------------------
// Init kernel: compute Cmin and E0 from C (once per launch, deterministic).
// ---------------------------------------------------------------------------
__global__ void ot_init_kernel(const float* __restrict__ C) {
    __shared__ float sred[8];
    __shared__ float scmin;
    const int tid = threadIdx.x;
    const int l = tid & 31, w = tid >> 5;

    float m = 3.402823466e38f;
    for (int k = tid; k < B_DIM * N_DIM; k += 256)
        m = fminf(m, C[k]);
    #pragma unroll
    for (int o = 16; o; o >>= 1)
        m = fminf(m, __shfl_xor_sync(0xFFFFFFFFu, m, o));
    if (l == 0) sred[w] = m;
    __syncthreads();
    if (tid == 0) {
        float mm = sred[0];
        #pragma unroll
        for (int k = 1; k < 8; k++) mm = fminf(mm, sred[k]);
        scmin = mm;
        g_Cmin = mm;
    }
    __syncthreads();
    const float cmin = scmin;
    for (int k = tid; k < B_DIM * N_DIM; k += 256)
        g_E0[k] = __expf((cmin - C[k]) * INV_EPS);
}

// ---------------------------------------------------------------------------
// Main kernel: one block (256 threads) per sample.
//  - E0 read directly from global (L1-resident); no smem copy of the matrix.
//  - u-update: warp w owns rows 8w..8w+7, float4 row dot + shfl reduce.
//  - v-update: thread tid owns column tid, coalesced column loads, with the
//    epilogue (sum_b pi*mu) fused as a second accumulator.
// ---------------------------------------------------------------------------
extern "C" __global__ void __launch_bounds__(256, 6)
ot_main_kernel(const float* __restrict__ mu,
               const float* __restrict__ nu,
               float* __restrict__ out) {
    __shared__ float sev[N_DIM];     // exp((v_j - m_v)/eps)
    __shared__ float seu[B_DIM];     // exp((u_i - m_u)/eps)
    __shared__ float swt[B_DIM];     // eu_i * mu_i
    __shared__ float su[B_DIM];      // current u
    __shared__ float slogmu[B_DIM];  // log(mu + LOG_EPS)
    __shared__ float smu[B_DIM];     // mu
    __shared__ float sdu[B_DIM];     // |du| per row
    __shared__ float sred[16];       // [0..7] m_v partials, [8]=err, [9]=m_u

    const int s   = blockIdx.x;
    const int tid = threadIdx.x;
    const int l   = tid & 31;
    const int w   = tid >> 5;

    if (tid < B_DIM) {
        float m = mu[s * B_DIM + tid];
        smu[tid]    = m;
        slogmu[tid] = __logf(m + LOG_EPS);
        su[tid]     = 0.0f;
    }
    const float lognu = __logf(nu[s * N_DIM + tid] + LOG_EPS);
    sev[tid] = 1.0f;              // v = 0, m_v = 0 -> ev = 1
    const float cmin = g_Cmin;
    __syncthreads();

    float m_v = 0.0f;
    float m_u = 0.0f;
    float my_ev = 1.0f;
    float acc2 = 0.0f;            // fused epilogue accumulator

    for (int it = 0; it < MAX_ITER; ++it) {
        // ---- u update: warp w handles rows 8w..8w+7 ----
        const float4 evA = reinterpret_cast<const float4*>(sev)[l];
        const float4 evB = reinterpret_cast<const float4*>(sev)[32 + l];
        #pragma unroll
        for (int r = 0; r < 8; ++r) {
            const int row = (w << 3) + r;
            const float4* e4 = reinterpret_cast<const float4*>(g_E0 + (row << 8));
            const float4 a = __ldg(e4 + l);
            const float4 b = __ldg(e4 + 32 + l);
            float p = a.x * evA.x + a.y * evA.y + a.z * evA.z + a.w * evA.w
                    + b.x * evB.x + b.y * evB.y + b.z * evB.z + b.w * evB.w;
            #pragma unroll
            for (int o = 16; o; o >>= 1)
                p += __shfl_xor_sync(0xFFFFFFFFu, p, o);
            if (l == r) {
                float unew = EPSV * slogmu[row] - (m_v - cmin) - EPSV * __logf(p);
                sdu[row] = fabsf(unew - su[row]);
                su[row]  = unew;
            }
        }
        __syncthreads();

        // ---- reduce err = sum |du|, m_u = max u ----
        if (w == 0) {
            float d  = sdu[l] + sdu[l + 32];
            float um = fmaxf(su[l], su[l + 32]);
            #pragma unroll
            for (int o = 16; o; o >>= 1) {
                d += __shfl_xor_sync(0xFFFFFFFFu, d, o);
                um = fmaxf(um, __shfl_xor_sync(0xFFFFFFFFu, um, o));
            }
            if (l == 0) { sred[8] = d; sred[9] = um; }
        }
        __syncthreads();
        const float err = sred[8];
        m_u = sred[9];
        if (tid < B_DIM) {
            const float eu = __expf((su[tid] - m_u) * INV_EPS);
            seu[tid] = eu;
            swt[tid] = eu * smu[tid];
        }
        __syncthreads();

        const bool isLast = (err < THRESH) || (it == MAX_ITER - 1);

        // ---- v update: thread tid owns column tid (coalesced LDG, L1-hit) ----
        {
            const float* col = g_E0 + tid;
            float a0 = 0.0f, a1 = 0.0f;   // sum E0_bn * eu_b
            float b0 = 0.0f, b1 = 0.0f;   // sum E0_bn * eu_b * mu_b
            #pragma unroll
            for (int i = 0; i < B_DIM; i += 4) {
                const float4 e  = reinterpret_cast<const float4*>(seu)[i >> 2];
                const float4 wt = reinterpret_cast<const float4*>(swt)[i >> 2];
                const float c0 = __ldg(col + ((i    ) << 8));
                const float c1 = __ldg(col + ((i + 1) << 8));
                const float c2 = __ldg(col + ((i + 2) << 8));
                const float c3 = __ldg(col + ((i + 3) << 8));
                a0 = fmaf(c0, e.x,  a0);
                a1 = fmaf(c1, e.y,  a1);
                a0 = fmaf(c2, e.z,  a0);
                a1 = fmaf(c3, e.w,  a1);
                b0 = fmaf(c0, wt.x, b0);
                b1 = fmaf(c1, wt.y, b1);
                b0 = fmaf(c2, wt.z, b0);
                b1 = fmaf(c3, wt.w, b1);
            }
            const float accv = a0 + a1;
            acc2 = b0 + b1;
            const float v = EPSV * lognu - (m_u - cmin) - EPSV * __logf(accv);

            // block-reduce m_v
            float mv = v;
            #pragma unroll
            for (int o = 16; o; o >>= 1)
                mv = fmaxf(mv, __shfl_xor_sync(0xFFFFFFFFu, mv, o));
            if (l == 0) sred[w] = mv;
            __syncthreads();
            mv = sred[0];
            #pragma unroll
            for (int k = 1; k < 8; k++) mv = fmaxf(mv, sred[k]);
            m_v = mv;
            my_ev = __expf((v - m_v) * INV_EPS);
            sev[tid] = my_ev;
        }
        __syncthreads();

        if (isLast) break;
    }

    // ---- out[s,n] = scale * ev_n * acc2_n ----
    const float scale = __expf((m_u + m_v - cmin) * INV_EPS);
    out[s * N_DIM + tid] = scale * my_ev * acc2;
}

// ---------------------------------------------------------------------------
// Launch
// ---------------------------------------------------------------------------
extern "C" void kernel_launch(void* const* d_in, const int* in_sizes, int n_in,
                              void* d_out, int out_size) {
    const float* mu = nullptr;
    const float* nu = nullptr;
    const float* C  = nullptr;
    for (int i = 0; i < n_in; ++i) {
        if (in_sizes[i] == S_TOT * B_DIM)      mu = (const float*)d_in[i];
        else if (in_sizes[i] == S_TOT * N_DIM) nu = (const float*)d_in[i];
        else if (in_sizes[i] == B_DIM * N_DIM) C  = (const float*)d_in[i];
    }
    float* out = (float*)d_out;

    ot_init_kernel<<<1, 256>>>(C);
    ot_main_kernel<<<S_TOT, 256>>>(mu, nu, out);
}

// round 4
// speedup vs baseline: 2.6477x; 2.6477x over previous
#include <cuda_runtime.h>
#include <math_constants.h>

#define S_TOT 2048
#define B_DIM 64
#define N_DIM 256
#define EPSV 0.01f
#define INV_EPS 100.0f
#define THRESH 0.1f
#define MAX_ITER 100
#define LOG_EPS 1e-8f

#define SAMPLES_PER_BLK 2
#define THREADS (256 * SAMPLES_PER_BLK)
#define SUB_STRIDE 656   // floats of per-sample smem (256+6*64+16)

// Global: E0_ij = exp((Cmin - C_ij)/eps), identical for all samples.
__device__ float g_E0[B_DIM * N_DIM];
__device__ float g_Cmin;

// ---------------------------------------------------------------------------
// Init kernel: compute Cmin and E0 from C (once per launch, deterministic).
// ---------------------------------------------------------------------------
__global__ void ot_init_kernel(const float* __restrict__ C) {
    __shared__ float sred[8];
    __shared__ float scmin;
    const int tid = threadIdx.x;
    const int l = tid & 31, w = tid >> 5;

    float m = 3.402823466e38f;
    for (int k = tid; k < B_DIM * N_DIM; k += 256)
        m = fminf(m, C[k]);
    #pragma unroll
    for (int o = 16; o; o >>= 1)
        m = fminf(m, __shfl_xor_sync(0xFFFFFFFFu, m, o));
    if (l == 0) sred[w] = m;
    __syncthreads();
    if (tid == 0) {
        float mm = sred[0];
        #pragma unroll
        for (int k = 1; k < 8; k++) mm = fminf(mm, sred[k]);
        scmin = mm;
        g_Cmin = mm;
    }
    __syncthreads();
    const float cmin = scmin;
    for (int k = tid; k < B_DIM * N_DIM; k += 256)
        g_E0[k] = __expf((cmin - C[k]) * INV_EPS);
}

// ---------------------------------------------------------------------------
// Main kernel: 2 samples per block (512 threads), ONE shared E0 copy.
// Threads [0,256) -> sample 0 of the pair, [256,512) -> sample 1.
// Per-sample logic identical to the 53us R1 kernel + fused epilogue.
// Per-sample convergence via 'active' guard; barriers unconditional.
// ---------------------------------------------------------------------------
extern "C" __global__ void __launch_bounds__(THREADS, 3)
ot_main_kernel(const float* __restrict__ mu,
               const float* __restrict__ nu,
               float* __restrict__ out) {
    extern __shared__ float sm[];
    float* sE0 = sm;                               // [16384] shared by both samples
    const int tid  = threadIdx.x;
    const int sub  = tid >> 8;                     // sample slot within block
    const int stid = tid & 255;                    // thread id within sample
    const int l    = stid & 31;
    const int ws   = stid >> 5;                    // warp within sample (0..7)

    float* base   = sm + 16384 + sub * SUB_STRIDE;
    float* sev    = base;            // [256]
    float* seu    = base + 256;      // [64]
    float* swt    = base + 320;      // [64]
    float* su     = base + 384;      // [64]
    float* slogmu = base + 448;      // [64]
    float* smu    = base + 512;      // [64]
    float* sdu    = base + 576;      // [64]
    float* sred   = base + 640;      // [16]  [0..7]=m_v partials [8]=err [9]=m_u

    const int s = blockIdx.x * SAMPLES_PER_BLK + sub;

    // ---- stage E0 into shared (64KB, float4 coalesced, plain LDG) ----
    {
        const float4* g4 = reinterpret_cast<const float4*>(g_E0);
        float4* s4 = reinterpret_cast<float4*>(sE0);
        #pragma unroll
        for (int k = 0; k < 4096 / THREADS; k++)
            s4[tid + THREADS * k] = g4[tid + THREADS * k];
    }
    if (stid < B_DIM) {
        float m = mu[s * B_DIM + stid];
        smu[stid]    = m;
        slogmu[stid] = __logf(m + LOG_EPS);
        su[stid]     = 0.0f;
    }
    const float lognu = __logf(nu[s * N_DIM + stid] + LOG_EPS);
    sev[stid] = 1.0f;               // v = 0, m_v = 0 -> ev = 1
    const float cmin = g_Cmin;
    __syncthreads();

    float m_v = 0.0f;
    float m_u = 0.0f;
    float my_ev = 1.0f;
    float acc2 = 0.0f;              // fused epilogue accumulator
    bool  active = true;            // uniform across the 256 threads of a sample

    for (int it = 0; it < MAX_ITER; ++it) {
        // ---- u update: warp ws handles rows 8ws..8ws+7 ----
        if (active) {
            const float4 evA = reinterpret_cast<const float4*>(sev)[l];
            const float4 evB = reinterpret_cast<const float4*>(sev)[32 + l];
            #pragma unroll
            for (int r = 0; r < 8; ++r) {
                const int row = (ws << 3) + r;
                const float4* e4 = reinterpret_cast<const float4*>(sE0 + (row << 8));
                const float4 a = e4[l];
                const float4 b = e4[32 + l];
                float p = a.x * evA.x + a.y * evA.y + a.z * evA.z + a.w * evA.w
                        + b.x * evB.x + b.y * evB.y + b.z * evB.z + b.w * evB.w;
                #pragma unroll
                for (int o = 16; o; o >>= 1)
                    p += __shfl_xor_sync(0xFFFFFFFFu, p, o);
                if (l == r) {
                    float unew = EPSV * slogmu[row] - (m_v - cmin) - EPSV * __logf(p);
                    sdu[row] = fabsf(unew - su[row]);
                    su[row]  = unew;
                }
            }
        }
        __syncthreads();

        // ---- reduce err = sum |du|, m_u = max u (harmless if frozen) ----
        if (ws == 0) {
            float d  = sdu[l] + sdu[l + 32];
            float um = fmaxf(su[l], su[l + 32]);
            #pragma unroll
            for (int o = 16; o; o >>= 1) {
                d += __shfl_xor_sync(0xFFFFFFFFu, d, o);
                um = fmaxf(um, __shfl_xor_sync(0xFFFFFFFFu, um, o));
            }
            if (l == 0) { sred[8] = d; sred[9] = um; }
        }
        __syncthreads();
        const float err = sred[8];
        if (active) {
            m_u = sred[9];
            if (stid < B_DIM) {
                const float eu = __expf((su[stid] - m_u) * INV_EPS);
                seu[stid] = eu;
                swt[stid] = eu * smu[stid];
            }
        }
        __syncthreads();

        const bool isLast = err < THRESH || it == MAX_ITER - 1;

        // ---- v update: thread stid owns column stid; fused epilogue acc ----
        float v_loc = 0.0f;
        if (active) {
            const float* col = sE0 + stid;
            float a0 = 0.0f, a1 = 0.0f;   // sum E0_bn * eu_b
            float b0 = 0.0f, b1 = 0.0f;   // sum E0_bn * eu_b * mu_b
            #pragma unroll
            for (int i = 0; i < B_DIM; i += 4) {
                const float4 e  = reinterpret_cast<const float4*>(seu)[i >> 2];
                const float4 wt = reinterpret_cast<const float4*>(swt)[i >> 2];
                const float c0 = col[(i    ) << 8];
                const float c1 = col[(i + 1) << 8];
                const float c2 = col[(i + 2) << 8];
                const float c3 = col[(i + 3) << 8];
                a0 = fmaf(c0, e.x,  a0);
                a1 = fmaf(c1, e.y,  a1);
                a0 = fmaf(c2, e.z,  a0);
                a1 = fmaf(c3, e.w,  a1);
                b0 = fmaf(c0, wt.x, b0);
                b1 = fmaf(c1, wt.y, b1);
                b0 = fmaf(c2, wt.z, b0);
                b1 = fmaf(c3, wt.w, b1);
            }
            const float accv = a0 + a1;
            acc2 = b0 + b1;
            v_loc = EPSV * lognu - (m_u - cmin) - EPSV * __logf(accv);

            float mv = v_loc;
            #pragma unroll
            for (int o = 16; o; o >>= 1)
                mv = fmaxf(mv, __shfl_xor_sync(0xFFFFFFFFu, mv, o));
            if (l == 0) sred[ws] = mv;
        }
        __syncthreads();
        if (active) {
            float mv = sred[0];
            #pragma unroll
            for (int k = 1; k < 8; k++) mv = fmaxf(mv, sred[k]);
            m_v = mv;
            my_ev = __expf((v_loc - m_v) * INV_EPS);
            sev[stid] = my_ev;
            if (isLast) active = false;
        }
        if (!__syncthreads_or(active ? 1 : 0)) break;
    }

    // ---- out[s,n] = scale * ev_n * acc2_n ----
    const float scale = __expf((m_u + m_v - cmin) * INV_EPS);
    out[s * N_DIM + stid] = scale * my_ev * acc2;
}

// ---------------------------------------------------------------------------
// Launch
// ---------------------------------------------------------------------------
extern "C" void kernel_launch(void* const* d_in, const int* in_sizes, int n_in,
                              void* d_out, int out_size) {
    const float* mu = nullptr;
    const float* nu = nullptr;
    const float* C  = nullptr;
    for (int i = 0; i < n_in; ++i) {
        if (in_sizes[i] == S_TOT * B_DIM)      mu = (const float*)d_in[i];
        else if (in_sizes[i] == S_TOT * N_DIM) nu = (const float*)d_in[i];
        else if (in_sizes[i] == B_DIM * N_DIM) C  = (const float*)d_in[i];
    }
    float* out = (float*)d_out;

    const int smem_bytes = (16384 + SAMPLES_PER_BLK * SUB_STRIDE) * sizeof(float);
    cudaFuncSetAttribute(ot_main_kernel,
                         cudaFuncAttributeMaxDynamicSharedMemorySize, smem_bytes);

    ot_init_kernel<<<1, 256>>>(C);
    ot_main_kernel<<<S_TOT / SAMPLES_PER_BLK, THREADS, smem_bytes>>>(mu, nu, out);
}

// round 5
// speedup vs baseline: 3.0945x; 1.1688x over previous
#include <cuda_runtime.h>

#define S_TOT 2048
#define B_DIM 64
#define N_DIM 256
#define EPSV 0.01f
#define INV_EPS 100.0f
#define THRESH 0.1f
#define MAX_ITER 100
#define LOG_EPS 1e-8f
#define THREADS 512

// E0_ij = exp((Cmin - C_ij)/eps); row sums S_i (log and reciprocal).
__device__ float g_E0[B_DIM * N_DIM];
__device__ float g_logS[B_DIM];
__device__ float g_invS[B_DIM];
__device__ float g_Cmin;

// ---------------------------------------------------------------------------
// Init: Cmin, E0, and row sums of E0 (iter-0 u-update is ev==1 => row sums).
// ---------------------------------------------------------------------------
__global__ void ot_init_kernel(const float* __restrict__ C) {
    __shared__ float sred[8];
    __shared__ float scmin;
    const int tid = threadIdx.x;
    const int l = tid & 31, w = tid >> 5;

    float m = 3.402823466e38f;
    for (int k = tid; k < B_DIM * N_DIM; k += 256)
        m = fminf(m, C[k]);
    #pragma unroll
    for (int o = 16; o; o >>= 1)
        m = fminf(m, __shfl_xor_sync(0xFFFFFFFFu, m, o));
    if (l == 0) sred[w] = m;
    __syncthreads();
    if (tid == 0) {
        float mm = sred[0];
        #pragma unroll
        for (int k = 1; k < 8; k++) mm = fminf(mm, sred[k]);
        scmin = mm;
        g_Cmin = mm;
    }
    __syncthreads();
    const float cmin = scmin;
    for (int k = tid; k < B_DIM * N_DIM; k += 256)
        g_E0[k] = __expf((cmin - C[k]) * INV_EPS);
    __syncthreads();

    // Row sums: warp w handles rows 8w..8w+7.
    const float4* g4 = reinterpret_cast<const float4*>(g_E0);
    #pragma unroll
    for (int r = 0; r < 8; ++r) {
        const int row = (w << 3) + r;
        const float4 a = g4[(row << 6) + l];
        const float4 b = g4[(row << 6) + 32 + l];
        float p = a.x + a.y + a.z + a.w + b.x + b.y + b.z + b.w;
        #pragma unroll
        for (int o = 16; o; o >>= 1)
            p += __shfl_xor_sync(0xFFFFFFFFu, p, o);
        if (l == r) {
            g_logS[row] = __logf(p);
            g_invS[row] = 1.0f / p;
        }
    }
}

// ---------------------------------------------------------------------------
// Main: 2 samples/block, 512 threads, one shared E0.
//  - it=0 u-update from precomputed row sums (no matrix pass).
//  - u-pass (it>=1): per-sample, warps 0-7 sample0 / 8-15 sample1 (R4 layout).
//  - v-pass: SHARED — half h reads rows 32h..32h+31 once, FMAs into both
//    samples via packed euwt float4; halves combine via smem exchange;
//    h=0 finishes v/m_v/ev for BOTH samples and writes both outputs.
// smem floats: [0]E0 16384 | [16384]euwt 256 | [16640]spart 1024 (aliases sdu)
//  | [17664]snu1 256 | [17920]sev0 256 | [18176]sev1 256 | [18432]su 2x64
//  | [18560]slogmu 2x64 | [18688]smu 2x64 | [18816]sred 2x16  => 18848 total
// ---------------------------------------------------------------------------
extern "C" __global__ void __launch_bounds__(THREADS, 3)
ot_main_kernel(const float* __restrict__ mu,
               const float* __restrict__ nu,
               float* __restrict__ out) {
    extern __shared__ float sm[];
    const int tid = threadIdx.x;
    const int h   = tid >> 8;          // sample slot of this thread
    const int col = tid & 255;
    const int l   = tid & 31;
    const int w   = tid >> 5;          // 0..15
    const int ws  = w & 7;

    float*  sev_h  = sm + 17920 + (h << 8);
    float*  su_h   = sm + 18432 + (h << 6);
    float*  slm_h  = sm + 18560 + (h << 6);
    float*  smu_h  = sm + 18688 + (h << 6);
    float*  sred_h = sm + 18816 + (h << 4);
    float*  sdu_h  = sm + 16640 + (h << 6);          // alias into spart
    float*  sred0  = sm + 18816;
    float*  sred1  = sm + 18832;
    float4* euwt   = reinterpret_cast<float4*>(sm + 16384);
    float4* spart  = reinterpret_cast<float4*>(sm + 16640);
    float*  snu1   = sm + 17664;

    const int s0  = blockIdx.x * 2;
    const int s1  = s0 + 1;
    const int s_h = s0 + h;

    // ---- stage E0 (64KB, float4) ----
    {
        const float4* g4 = reinterpret_cast<const float4*>(g_E0);
        float4* s4 = reinterpret_cast<float4*>(sm);
        #pragma unroll
        for (int k = 0; k < 8; k++)
            s4[tid + THREADS * k] = g4[tid + THREADS * k];
    }
    if (col < B_DIM) {
        float m = mu[s_h * B_DIM + col];
        smu_h[col] = m;
        slm_h[col] = __logf(m + LOG_EPS);
    }
    const float eps_lognu = EPSV * __logf(nu[s_h * N_DIM + col] + LOG_EPS);
    if (h) snu1[col] = eps_lognu;
    if (tid == 0) { sred0[10] = 0.0f; sred1[10] = 0.0f; }
    const float cmin = g_Cmin;
    __syncthreads();

    bool active0 = true, active1 = true;
    // output-state (meaningful on h==0 threads)
    float ev0 = 0.f, ev1 = 0.f, ac0 = 0.f, ac1 = 0.f;
    float mu0f = cmin, mu1f = cmin, mv0f = 0.f, mv1f = 0.f;

    for (int it = 0; it < MAX_ITER; ++it) {
        const bool act_h = h ? active1 : active0;

        // ---- u phase ----
        if (it == 0) {
            if (col < B_DIM) {
                const float u1 = EPSV * (slm_h[col] - g_logS[col]) + cmin;
                su_h[col]  = u1;
                sdu_h[col] = fabsf(u1);      // u was 0
            }
        } else if (act_h) {
            const float m_v_h = sred_h[10];
            const float4 evA = reinterpret_cast<const float4*>(sev_h)[l];
            const float4 evB = reinterpret_cast<const float4*>(sev_h)[32 + l];
            #pragma unroll
            for (int r = 0; r < 8; ++r) {
                const int row = (ws << 3) + r;
                const float4* e4 = reinterpret_cast<const float4*>(sm + (row << 8));
                const float4 a = e4[l];
                const float4 b = e4[32 + l];
                float p = a.x * evA.x + a.y * evA.y + a.z * evA.z + a.w * evA.w
                        + b.x * evB.x + b.y * evB.y + b.z * evB.z + b.w * evB.w;
                #pragma unroll
                for (int o = 16; o; o >>= 1)
                    p += __shfl_xor_sync(0xFFFFFFFFu, p, o);
                if (l == r) {
                    const float unew = EPSV * slm_h[row] - (m_v_h - cmin)
                                     - EPSV * __logf(p);
                    sdu_h[row] = fabsf(unew - su_h[row]);
                    su_h[row]  = unew;
                }
            }
        }
        __syncthreads();                                        // B1

        // ---- err / m_u reduce: warp 0 -> sample0, warp 8 -> sample1 ----
        if (ws == 0) {
            float d  = sdu_h[l] + sdu_h[l + 32];
            float um = fmaxf(su_h[l], su_h[l + 32]);
            #pragma unroll
            for (int o = 16; o; o >>= 1) {
                d  += __shfl_xor_sync(0xFFFFFFFFu, d, o);
                um  = fmaxf(um, __shfl_xor_sync(0xFFFFFFFFu, um, o));
            }
            if (l == 0) { sred_h[8] = d; sred_h[9] = um; }
        }
        __syncthreads();                                        // B2
        const float err0 = sred0[8], err1 = sred1[8];

        // ---- euwt: (eu0, wt0, eu1, wt1) per row ----
        if (col < B_DIM && act_h) {
            const float eu = (it == 0)
                ? (smu_h[col] + LOG_EPS) * g_invS[col]          // exp((u1-cmin)/eps)
                : __expf((su_h[col] - sred_h[9]) * INV_EPS);
            float* q = reinterpret_cast<float*>(&euwt[col]);
            q[2 * h]     = eu;
            q[2 * h + 1] = eu * smu_h[col];
        }
        __syncthreads();                                        // B3

        // ---- shared v-pass: half h covers rows 32h..32h+31 of column col ----
        float av0 = 0.f, ae0 = 0.f, av1 = 0.f, ae1 = 0.f;
        {
            const float* cp = sm + (h << 13) + col;
            const float4* q4 = euwt + (h << 5);
            #pragma unroll
            for (int i = 0; i < 32; i++) {
                const float c = cp[i << 8];
                const float4 q = q4[i];
                av0 = fmaf(c, q.x, av0);
                ae0 = fmaf(c, q.y, ae0);
                av1 = fmaf(c, q.z, av1);
                ae1 = fmaf(c, q.w, ae1);
            }
        }
        if (h) spart[col] = make_float4(av0, ae0, av1, ae1);
        __syncthreads();                                        // B4

        float v0 = 0.f, v1 = 0.f;
        if (!h) {
            const float4 o4 = spart[col];
            av0 += o4.x; ae0 += o4.y; av1 += o4.z; ae1 += o4.w;
            const float mue0 = (it == 0) ? cmin : sred0[9];
            const float mue1 = (it == 0) ? cmin : sred1[9];
            v0 = eps_lognu - (mue0 - cmin) - EPSV * __logf(av0);
            v1 = snu1[col] - (mue1 - cmin) - EPSV * __logf(av1);
            float m0 = v0, m1 = v1;
            #pragma unroll
            for (int o = 16; o; o >>= 1) {
                m0 = fmaxf(m0, __shfl_xor_sync(0xFFFFFFFFu, m0, o));
                m1 = fmaxf(m1, __shfl_xor_sync(0xFFFFFFFFu, m1, o));
            }
            if (l == 0) { sred0[ws] = m0; sred1[ws] = m1; }
        }
        __syncthreads();                                        // B5

        if (!h) {
            float m0 = sred0[0], m1 = sred1[0];
            #pragma unroll
            for (int k = 1; k < 8; k++) {
                m0 = fmaxf(m0, sred0[k]);
                m1 = fmaxf(m1, sred1[k]);
            }
            if (active0) {
                const float e = __expf((v0 - m0) * INV_EPS);
                sm[17920 + col] = e;                            // sev0
                ev0 = e; ac0 = ae0; mv0f = m0;
                mu0f = (it == 0) ? cmin : sred0[9];
                if (tid == 0) sred0[10] = m0;
            }
            if (active1) {
                const float e = __expf((v1 - m1) * INV_EPS);
                sm[18176 + col] = e;                            // sev1
                ev1 = e; ac1 = ae1; mv1f = m1;
                mu1f = (it == 0) ? cmin : sred1[9];
                if (tid == 0) sred1[10] = m1;
            }
        }
        __syncthreads();                                        // B6

        if (active0 && (err0 < THRESH || it == MAX_ITER - 1)) active0 = false;
        if (active1 && (err1 < THRESH || it == MAX_ITER - 1)) active1 = false;
        if (!active0 && !active1) break;
    }

    // ---- outputs (h==0 threads write both samples' rows) ----
    if (!h) {
        out[s0 * N_DIM + col] = __expf((mu0f + mv0f - cmin) * INV_EPS) * ev0 * ac0;
        out[s1 * N_DIM + col] = __expf((mu1f + mv1f - cmin) * INV_EPS) * ev1 * ac1;
    }
}

// ---------------------------------------------------------------------------
// Launch
// ---------------------------------------------------------------------------
extern "C" void kernel_launch(void* const* d_in, const int* in_sizes, int n_in,
                              void* d_out, int out_size) {
    const float* mu = nullptr;
    const float* nu = nullptr;
    const float* C  = nullptr;
    for (int i = 0; i < n_in; ++i) {
        if (in_sizes[i] == S_TOT * B_DIM)      mu = (const float*)d_in[i];
        else if (in_sizes[i] == S_TOT * N_DIM) nu = (const float*)d_in[i];
        else if (in_sizes[i] == B_DIM * N_DIM) C  = (const float*)d_in[i];
    }
    float* out = (float*)d_out;

    const int smem_bytes = 18848 * sizeof(float);   // ~73.6 KB
    cudaFuncSetAttribute(ot_main_kernel,
                         cudaFuncAttributeMaxDynamicSharedMemorySize, smem_bytes);

    ot_init_kernel<<<1, 256>>>(C);
    ot_main_kernel<<<S_TOT / 2, THREADS, smem_bytes>>>(mu, nu, out);
}

// round 6
// speedup vs baseline: 4.0336x; 1.3035x over previous
#include <cuda_runtime.h>
#include <cuda_fp16.h>

#define S_TOT 2048
#define B_DIM 64
#define N_DIM 256
#define EPSV 0.01f
#define INV_EPS 100.0f
#define THRESH 0.1f
#define MAX_ITER 100
#define LOG_EPS 1e-8f
#define THREADS 512

// E0_ij = exp((Cmin - C_ij)/eps) in fp16 (values in (0,1]); row sums in fp32.
__device__ __align__(16) __half g_E0h[B_DIM * N_DIM];
__device__ float g_logS[B_DIM];
__device__ float g_invS[B_DIM];
__device__ float g_Cmin;

// ---------------------------------------------------------------------------
// Init (1 block, 1024 threads): cmin, E0h, row sums.
// ---------------------------------------------------------------------------
__global__ void __launch_bounds__(1024) ot_init_kernel(const float* __restrict__ C) {
    __shared__ float sred[33];
    const int tid = threadIdx.x;
    const int l = tid & 31, w = tid >> 5;

    const float4* C4 = reinterpret_cast<const float4*>(C);
    float4 cv[4];
    float mn = 3.402823466e38f;
    #pragma unroll
    for (int k = 0; k < 4; k++) {
        cv[k] = C4[tid + 1024 * k];
        mn = fminf(mn, fminf(fminf(cv[k].x, cv[k].y), fminf(cv[k].z, cv[k].w)));
    }
    #pragma unroll
    for (int o = 16; o; o >>= 1)
        mn = fminf(mn, __shfl_xor_sync(0xFFFFFFFFu, mn, o));
    if (l == 0) sred[w] = mn;
    __syncthreads();
    if (w == 0) {
        float t = sred[l];
        #pragma unroll
        for (int o = 16; o; o >>= 1)
            t = fminf(t, __shfl_xor_sync(0xFFFFFFFFu, t, o));
        if (l == 0) { sred[32] = t; g_Cmin = t; }
    }
    __syncthreads();
    const float cmin = sred[32];

    __half2* g2 = reinterpret_cast<__half2*>(g_E0h);
    #pragma unroll
    for (int k = 0; k < 4; k++) {
        const float4 c = cv[k];
        g2[(tid + 1024 * k) * 2] =
            __floats2half2_rn(__expf((cmin - c.x) * INV_EPS), __expf((cmin - c.y) * INV_EPS));
        g2[(tid + 1024 * k) * 2 + 1] =
            __floats2half2_rn(__expf((cmin - c.z) * INV_EPS), __expf((cmin - c.w) * INV_EPS));
    }
    __syncthreads();   // block-scope fence: E0h visible to this block

    // Row sums: warp w handles rows 2w, 2w+1.
    #pragma unroll
    for (int rr = 0; rr < 2; rr++) {
        const int row = w * 2 + rr;
        const int4 hv = reinterpret_cast<const int4*>(g_E0h + row * N_DIM)[l];
        const __half2* hp = reinterpret_cast<const __half2*>(&hv);
        const float2 f0 = __half22float2(hp[0]), f1 = __half22float2(hp[1]);
        const float2 f2 = __half22float2(hp[2]), f3 = __half22float2(hp[3]);
        float p = f0.x + f0.y + f1.x + f1.y + f2.x + f2.y + f3.x + f3.y;
        #pragma unroll
        for (int o = 16; o; o >>= 1)
            p += __shfl_xor_sync(0xFFFFFFFFu, p, o);
        if (l == 0) { g_logS[row] = __logf(p); g_invS[row] = 1.0f / p; }
    }
}

// smem layout (float offsets); E0h occupies floats [0,8192) as half[16384].
#define O_EUWT  8192    // float4[64]: (eu0, wt0, eu1, wt1)
#define O_SPART 8448    // spartA float4[384] @8448, spartB float4[384] @9984
#define O_SDU   8448    // alias: sdu_h = O_SDU + h*64 (temporally disjoint)
#define O_SNU   11520   // snu0 [256], snu1 [256]
#define O_SEV   12032   // sev0 [256], sev1 [256]
#define O_SU    12544   // 2 x 64
#define O_SLM   12672
#define O_SMU   12800
#define O_SRED  12928   // 2 x 16: [0..7]=mv partials, [8]=err, [9]=m_u, [10]=m_v
#define SMEM_FLOATS 12960

// ---------------------------------------------------------------------------
// Main: 2 samples/block, 512 threads, fp16 E0 in shared.
//  - it=0 u-update from precomputed row sums.
//  - u-pass (it>=1): per-sample; warp reads rows as int4 (8 halves/lane).
//  - v-pass: thread = (row-quarter qr, col-pair cp); one half2 load covers
//    2 columns; outputs written directly on each sample's last iteration.
// ---------------------------------------------------------------------------
extern "C" __global__ void __launch_bounds__(THREADS, 3)
ot_main_kernel(const float* __restrict__ mu,
               const float* __restrict__ nu,
               float* __restrict__ out) {
    extern __shared__ float sm[];
    __half* sE0h = reinterpret_cast<__half*>(sm);

    const int tid = threadIdx.x;
    const int h   = tid >> 8;          // sample slot (u/euwt mapping)
    const int col = tid & 255;
    const int l   = tid & 31;
    const int w   = tid >> 5;          // 0..15
    const int ws  = w & 7;
    const int qr  = tid >> 7;          // row-quarter (v mapping)
    const int cp  = tid & 127;         // col-pair

    float* snu0   = sm + O_SNU;
    float* snu1   = sm + O_SNU + 256;
    float* sev_h  = sm + O_SEV + (h << 8);
    float* su_h   = sm + O_SU  + (h << 6);
    float* slm_h  = sm + O_SLM + (h << 6);
    float* smu_h  = sm + O_SMU + (h << 6);
    float* sred0  = sm + O_SRED;
    float* sred1  = sm + O_SRED + 16;
    float* sred_h = sm + O_SRED + (h << 4);
    float* sdu_h  = sm + O_SDU + (h << 6);
    float4* spartA = reinterpret_cast<float4*>(sm + O_SPART);
    float4* spartB = spartA + 384;

    const int s0 = blockIdx.x * 2, s1 = s0 + 1, s_h = s0 + h;

    // ---- stage E0h (32KB, uint4) ----
    {
        const uint4* g4 = reinterpret_cast<const uint4*>(g_E0h);
        uint4* s4 = reinterpret_cast<uint4*>(sE0h);
        #pragma unroll
        for (int k = 0; k < 4; k++)
            s4[tid + THREADS * k] = g4[tid + THREADS * k];
    }
    if (col < B_DIM) {
        const float m = mu[s_h * B_DIM + col];
        smu_h[col] = m;
        slm_h[col] = __logf(m + LOG_EPS);
    }
    sm[O_SNU + (h << 8) + col] = EPSV * __logf(nu[s_h * N_DIM + col] + LOG_EPS);
    if (tid == 0) { sred0[10] = 0.0f; sred1[10] = 0.0f; }
    const float cmin = g_Cmin;
    __syncthreads();

    bool active0 = true, active1 = true;

    for (int it = 0; it < MAX_ITER; ++it) {
        const bool act_h = h ? active1 : active0;

        // ---- u phase ----
        if (it == 0) {
            if (col < B_DIM) {
                const float u1 = EPSV * (slm_h[col] - g_logS[col]) + cmin;
                su_h[col]  = u1;
                sdu_h[col] = fabsf(u1);
            }
        } else if (act_h) {
            const float m_v_h = sred_h[10];
            const float4 evA = reinterpret_cast<const float4*>(sev_h)[2 * l];
            const float4 evB = reinterpret_cast<const float4*>(sev_h)[2 * l + 1];
            #pragma unroll
            for (int r = 0; r < 8; ++r) {
                const int row = (ws << 3) + r;
                const int4 hv = reinterpret_cast<const int4*>(sE0h + (row << 8))[l];
                const __half2* hp = reinterpret_cast<const __half2*>(&hv);
                const float2 f0 = __half22float2(hp[0]);
                const float2 f1 = __half22float2(hp[1]);
                const float2 f2 = __half22float2(hp[2]);
                const float2 f3 = __half22float2(hp[3]);
                float p = f0.x * evA.x + f0.y * evA.y + f1.x * evA.z + f1.y * evA.w
                        + f2.x * evB.x + f2.y * evB.y + f3.x * evB.z + f3.y * evB.w;
                #pragma unroll
                for (int o = 16; o; o >>= 1)
                    p += __shfl_xor_sync(0xFFFFFFFFu, p, o);
                if (l == r) {
                    const float unew = EPSV * slm_h[row] - (m_v_h - cmin)
                                     - EPSV * __logf(p);
                    sdu_h[row] = fabsf(unew - su_h[row]);
                    su_h[row]  = unew;
                }
            }
        }
        __syncthreads();                                        // B1

        // ---- err / m_u reduce (warps 0 and 8) ----
        if (ws == 0) {
            float d  = sdu_h[l] + sdu_h[l + 32];
            float um = fmaxf(su_h[l], su_h[l + 32]);
            #pragma unroll
            for (int o = 16; o; o >>= 1) {
                d  += __shfl_xor_sync(0xFFFFFFFFu, d, o);
                um  = fmaxf(um, __shfl_xor_sync(0xFFFFFFFFu, um, o));
            }
            if (l == 0) { sred_h[8] = d; sred_h[9] = um; }
        }
        __syncthreads();                                        // B2
        const float err0 = sred0[8], err1 = sred1[8];
        const bool last0 = active0 && (err0 < THRESH || it == MAX_ITER - 1);
        const bool last1 = active1 && (err1 < THRESH || it == MAX_ITER - 1);

        // ---- euwt: (eu0, wt0, eu1, wt1) per row ----
        if (col < B_DIM && act_h) {
            const float eu = (it == 0)
                ? (smu_h[col] + LOG_EPS) * g_invS[col]
                : __expf((su_h[col] - sred_h[9]) * INV_EPS);
            float* qp = sm + O_EUWT + (col << 2);
            qp[2 * h]     = eu;
            qp[2 * h + 1] = eu * smu_h[col];
        }
        __syncthreads();                                        // B3

        // ---- v phase: thread (qr, cp) -> cols {2cp, 2cp+1}, rows 16qr..+15 ----
        float av0a = 0, av0b = 0, ae0a = 0, ae0b = 0;
        float av1a = 0, av1b = 0, ae1a = 0, ae1b = 0;
        {
            const __half2* cph = reinterpret_cast<const __half2*>(sE0h)
                               + (qr << 11) + cp;               // row base qr*16*128
            const float4* qw = reinterpret_cast<const float4*>(sm + O_EUWT) + (qr << 4);
            #pragma unroll
            for (int i = 0; i < 16; i++) {
                const float2 cf = __half22float2(cph[i << 7]);
                const float4 q  = qw[i];
                av0a = fmaf(cf.x, q.x, av0a); av0b = fmaf(cf.y, q.x, av0b);
                ae0a = fmaf(cf.x, q.y, ae0a); ae0b = fmaf(cf.y, q.y, ae0b);
                av1a = fmaf(cf.x, q.z, av1a); av1b = fmaf(cf.y, q.z, av1b);
                ae1a = fmaf(cf.x, q.w, ae1a); ae1b = fmaf(cf.y, q.w, ae1b);
            }
        }
        if (qr) {
            spartA[((qr - 1) << 7) + cp] = make_float4(av0a, ae0a, av1a, ae1a);
            spartB[((qr - 1) << 7) + cp] = make_float4(av0b, ae0b, av1b, ae1b);
        }
        __syncthreads();                                        // B4

        float v0a = 0, v0b = 0, v1a = 0, v1b = 0, m0 = 0, m1 = 0;
        if (qr == 0) {
            #pragma unroll
            for (int t = 0; t < 3; t++) {
                const float4 pa = spartA[(t << 7) + cp];
                const float4 pb = spartB[(t << 7) + cp];
                av0a += pa.x; ae0a += pa.y; av1a += pa.z; ae1a += pa.w;
                av0b += pb.x; ae0b += pb.y; av1b += pb.z; ae1b += pb.w;
            }
            const float2 ln0 = *reinterpret_cast<const float2*>(snu0 + 2 * cp);
            const float2 ln1 = *reinterpret_cast<const float2*>(snu1 + 2 * cp);
            const float mue0 = (it == 0) ? cmin : sred0[9];
            const float mue1 = (it == 0) ? cmin : sred1[9];
            v0a = ln0.x - (mue0 - cmin) - EPSV * __logf(av0a);
            v0b = ln0.y - (mue0 - cmin) - EPSV * __logf(av0b);
            v1a = ln1.x - (mue1 - cmin) - EPSV * __logf(av1a);
            v1b = ln1.y - (mue1 - cmin) - EPSV * __logf(av1b);
            m0 = fmaxf(v0a, v0b);
            m1 = fmaxf(v1a, v1b);
            #pragma unroll
            for (int o = 16; o; o >>= 1) {
                m0 = fmaxf(m0, __shfl_xor_sync(0xFFFFFFFFu, m0, o));
                m1 = fmaxf(m1, __shfl_xor_sync(0xFFFFFFFFu, m1, o));
            }
            if (l == 0) { sred0[w] = m0; sred1[w] = m1; }       // w = 0..3 here
        }
        __syncthreads();                                        // B5

        if (qr == 0) {
            m0 = fmaxf(fmaxf(sred0[0], sred0[1]), fmaxf(sred0[2], sred0[3]));
            m1 = fmaxf(fmaxf(sred1[0], sred1[1]), fmaxf(sred1[2], sred1[3]));
            if (active0) {
                const float e0a = __expf((v0a - m0) * INV_EPS);
                const float e0b = __expf((v0b - m0) * INV_EPS);
                sm[O_SEV + 2 * cp]     = e0a;
                sm[O_SEV + 2 * cp + 1] = e0b;
                if (tid == 0) sred0[10] = m0;
                if (last0) {
                    const float mue0 = (it == 0) ? cmin : sred0[9];
                    const float sc = __expf((mue0 + m0 - cmin) * INV_EPS);
                    out[s0 * N_DIM + 2 * cp]     = sc * e0a * ae0a;
                    out[s0 * N_DIM + 2 * cp + 1] = sc * e0b * ae0b;
                }
            }
            if (active1) {
                const float e1a = __expf((v1a - m1) * INV_EPS);
                const float e1b = __expf((v1b - m1) * INV_EPS);
                sm[O_SEV + 256 + 2 * cp]     = e1a;
                sm[O_SEV + 256 + 2 * cp + 1] = e1b;
                if (tid == 0) sred1[10] = m1;
                if (last1) {
                    const float mue1 = (it == 0) ? cmin : sred1[9];
                    const float sc = __expf((mue1 + m1 - cmin) * INV_EPS);
                    out[s1 * N_DIM + 2 * cp]     = sc * e1a * ae1a;
                    out[s1 * N_DIM + 2 * cp + 1] = sc * e1b * ae1b;
                }
            }
        }
        __syncthreads();                                        // B6

        if (last0) active0 = false;
        if (last1) active1 = false;
        if (!active0 && !active1) break;
    }
}

// ---------------------------------------------------------------------------
// Launch
// ---------------------------------------------------------------------------
extern "C" void kernel_launch(void* const* d_in, const int* in_sizes, int n_in,
                              void* d_out, int out_size) {
    const float* mu = nullptr;
    const float* nu = nullptr;
    const float* C  = nullptr;
    for (int i = 0; i < n_in; ++i) {
        if (in_sizes[i] == S_TOT * B_DIM)      mu = (const float*)d_in[i];
        else if (in_sizes[i] == S_TOT * N_DIM) nu = (const float*)d_in[i];
        else if (in_sizes[i] == B_DIM * N_DIM) C  = (const float*)d_in[i];
    }
    float* out = (float*)d_out;

    const int smem_bytes = SMEM_FLOATS * sizeof(float);   // ~50.6 KB
    cudaFuncSetAttribute(ot_main_kernel,
                         cudaFuncAttributeMaxDynamicSharedMemorySize, smem_bytes);

    ot_init_kernel<<<1, 1024>>>(C);
    ot_main_kernel<<<S_TOT / 2, THREADS, smem_bytes>>>(mu, nu, out);
}